// round 4
// baseline (speedup 1.0000x reference)
#include <cuda_runtime.h>

// ---------------------------------------------------------------------------
// MultiScaleTimeMixer: B=2048, T=128, C=128, scales {128, 64, 32}
// All stages expressed as GEMMs vs pre-masked / pre-transposed K-major weights.
// ---------------------------------------------------------------------------

#define NB 2048

// ---- scratch (static __device__ arrays: allocation-free) ----
__device__ float g_mu[NB];
__device__ float g_rs[NB];
__device__ float g_Wt0a[128 * 128];   // tril-masked, K-major [k][j]
__device__ float g_Wt0b[128 * 128];
__device__ float g_Wt1a[64 * 64];
__device__ float g_Wt1b[64 * 64];
__device__ float g_Wt2a[32 * 32];
__device__ float g_Wt2b[32 * 32];
__device__ float g_Wc1[256 * 128];    // conv1 weight as [k = kk*128+ci][co]
__device__ float g_Wc2[512 * 128];    // conv2 weight as [k = kk*128+ci][co]
__device__ float g_t0[(long long)NB * 128 * 128]; // scale0 intermediate
__device__ float g_g1[(long long)NB * 128 * 64];  // conv1 out (b,co,s)
__device__ float g_u1[(long long)NB * 128 * 64];  // after triu1a+hsw
__device__ float g_g2[(long long)NB * 128 * 32];
__device__ float g_u2[(long long)NB * 128 * 32];

__device__ __forceinline__ float hswish(float v) {
    return v * fminf(fmaxf(v + 3.0f, 0.0f), 6.0f) * (1.0f / 6.0f);
}

// ---------------------------------------------------------------------------
// Per-batch LayerNorm stats: mean & rsqrt(var+eps) over 128*128 elements
// ---------------------------------------------------------------------------
__global__ void stats_k(const float* __restrict__ x) {
    int b = blockIdx.x;
    const float4* xp = (const float4*)(x + (long long)b * 16384);
    float s = 0.f, q = 0.f;
    for (int i = threadIdx.x; i < 4096; i += 256) {
        float4 v = xp[i];
        s += v.x + v.y + v.z + v.w;
        q += v.x * v.x + v.y * v.y + v.z * v.z + v.w * v.w;
    }
    #pragma unroll
    for (int o = 16; o > 0; o >>= 1) {
        s += __shfl_down_sync(0xffffffffu, s, o);
        q += __shfl_down_sync(0xffffffffu, q, o);
    }
    __shared__ float ss[8], qs[8];
    int w = threadIdx.x >> 5, l = threadIdx.x & 31;
    if (l == 0) { ss[w] = s; qs[w] = q; }
    __syncthreads();
    if (threadIdx.x == 0) {
        float S = 0.f, Q = 0.f;
        #pragma unroll
        for (int i = 0; i < 8; i++) { S += ss[i]; Q += qs[i]; }
        float mu = S * (1.f / 16384.f);
        float var = Q * (1.f / 16384.f) - mu * mu;
        g_mu[b] = mu;
        g_rs[b] = rsqrtf(var + 1e-5f);
    }
}

// ---------------------------------------------------------------------------
// Weight prep: tril-mask + transpose to K-major; conv weights to [k][co]
// ---------------------------------------------------------------------------
__global__ void prep_k(const float* __restrict__ W0a, const float* __restrict__ W0b,
                       const float* __restrict__ W1a, const float* __restrict__ W1b,
                       const float* __restrict__ W2a, const float* __restrict__ W2b,
                       const float* __restrict__ c1w, const float* __restrict__ c2w) {
    int tid = blockIdx.x * blockDim.x + threadIdx.x;
    int stride = gridDim.x * blockDim.x;
    for (int i = tid; i < 16384; i += stride) {
        int k = i >> 7, n = i & 127;
        float m = (k <= n) ? 1.f : 0.f;
        g_Wt0a[i] = m * W0a[n * 128 + k];
        g_Wt0b[i] = m * W0b[n * 128 + k];
    }
    for (int i = tid; i < 4096; i += stride) {
        int k = i >> 6, n = i & 63;
        float m = (k <= n) ? 1.f : 0.f;
        g_Wt1a[i] = m * W1a[n * 64 + k];
        g_Wt1b[i] = m * W1b[n * 64 + k];
    }
    for (int i = tid; i < 1024; i += stride) {
        int k = i >> 5, n = i & 31;
        float m = (k <= n) ? 1.f : 0.f;
        g_Wt2a[i] = m * W2a[n * 32 + k];
        g_Wt2b[i] = m * W2b[n * 32 + k];
    }
    for (int i = tid; i < 256 * 128; i += stride) {
        int co = i & 127, k = i >> 7;
        int ci = k & 127, kk = k >> 7;
        g_Wc1[i] = c1w[co * 256 + ci * 2 + kk];
    }
    for (int i = tid; i < 512 * 128; i += stride) {
        int co = i & 127, k = i >> 7;
        int ci = k & 127, kk = k >> 7;
        g_Wc2[i] = c2w[co * 512 + ci * 4 + kk];
    }
}

// ---------------------------------------------------------------------------
// Generic tiled GEMM: out = epilogue( A[M,KTOT] @ Wt[KTOT,BN] + bias )
//   NORM: A element (row,k) = (x - mu[b])*rs[b]*gamma[t,k] + beta[t,k], b=row>>7
//   hsw : apply hardswish
//   mode 0: out[row*BN + col]            (row-major)
//   mode 1: out[(row/RB)*S0 + row%RB + col*S2 + offs]  (folded transpose)
// ---------------------------------------------------------------------------
template<int BM, int BN, int BK, int TM, int TN, int KTOT, bool NORM>
__global__ __launch_bounds__(256, 2)
void gemm_k(const float* __restrict__ A, const float* __restrict__ Wt,
            const float* __restrict__ bias, float* __restrict__ out,
            int hsw, int mode, int RB, int S0, int S2, int offs,
            const float* __restrict__ gamma, const float* __restrict__ beta) {
    constexpr int NCOL = BN / TN;
    __shared__ float As[BK][BM + 4];
    __shared__ float Ws[BK][BN + 4];
    const int tid = threadIdx.x;
    const int tcol = tid % NCOL;
    const int trow = tid / NCOL;
    const long long row0 = (long long)blockIdx.x * BM;

    float acc[TM][TN];
    #pragma unroll
    for (int i = 0; i < TM; i++)
        #pragma unroll
        for (int j = 0; j < TN; j++) acc[i][j] = 0.f;

    for (int k0 = 0; k0 < KTOT; k0 += BK) {
        // ---- A tile (transpose to K-major in smem) ----
        constexpr int AQ = (BM * BK) / (4 * 256);
        #pragma unroll
        for (int qq = 0; qq < AQ; qq++) {
            int q = tid + qq * 256;
            int r = q >> 3;        // BK/4 == 8
            int kq = q & 7;
            long long grow = row0 + r;
            float4 v = *(const float4*)(A + grow * KTOT + k0 + kq * 4);
            if (NORM) {
                int b = (int)(grow >> 7);
                float m = g_mu[b], s = g_rs[b];
                int t = (int)(grow & 127);
                int c = k0 + kq * 4;
                float4 g = *(const float4*)(gamma + t * 128 + c);
                float4 be = *(const float4*)(beta + t * 128 + c);
                v.x = (v.x - m) * s * g.x + be.x;
                v.y = (v.y - m) * s * g.y + be.y;
                v.z = (v.z - m) * s * g.z + be.z;
                v.w = (v.w - m) * s * g.w + be.w;
            }
            As[kq * 4 + 0][r] = v.x;
            As[kq * 4 + 1][r] = v.y;
            As[kq * 4 + 2][r] = v.z;
            As[kq * 4 + 3][r] = v.w;
        }
        // ---- W tile (already K-major in gmem) ----
        constexpr int WQ = (BN * BK) / (4 * 256);
        #pragma unroll
        for (int qq = 0; qq < WQ; qq++) {
            int q = tid + qq * 256;
            int kk = q / (BN / 4);
            int nq = q % (BN / 4);
            *(float4*)&Ws[kk][nq * 4] = *(const float4*)(Wt + (k0 + kk) * BN + nq * 4);
        }
        __syncthreads();
        #pragma unroll
        for (int kk = 0; kk < BK; kk++) {
            float af[TM], wf[TN];
            #pragma unroll
            for (int iq = 0; iq < TM / 4; iq++)
                *(float4*)&af[iq * 4] = *(const float4*)&As[kk][trow * TM + iq * 4];
            #pragma unroll
            for (int jq = 0; jq < TN / 4; jq++)
                *(float4*)&wf[jq * 4] = *(const float4*)&Ws[kk][tcol * TN + jq * 4];
            #pragma unroll
            for (int i = 0; i < TM; i++)
                #pragma unroll
                for (int j = 0; j < TN; j++)
                    acc[i][j] += af[i] * wf[j];
        }
        __syncthreads();
    }

    // ---- bias + activation ----
    #pragma unroll
    for (int j = 0; j < TN; j++) {
        float bb = bias[tcol * TN + j];
        #pragma unroll
        for (int i = 0; i < TM; i++) {
            float v = acc[i][j] + bb;
            acc[i][j] = hsw ? hswish(v) : v;
        }
    }

    if (mode == 0) {
        #pragma unroll
        for (int i = 0; i < TM; i++) {
            long long grow = row0 + trow * TM + i;
            float* op = out + grow * BN + tcol * TN;
            #pragma unroll
            for (int jq = 0; jq < TN / 4; jq++) {
                float4 v = make_float4(acc[i][jq * 4 + 0], acc[i][jq * 4 + 1],
                                       acc[i][jq * 4 + 2], acc[i][jq * 4 + 3]);
                *(float4*)(op + jq * 4) = v;
            }
        }
    } else {
        #pragma unroll
        for (int j = 0; j < TN; j++) {
            int col = tcol * TN + j;
            #pragma unroll
            for (int iq = 0; iq < TM / 4; iq++) {
                long long grow = row0 + trow * TM + iq * 4;
                long long qb = grow / RB;
                int rrem = (int)(grow % RB);
                float* op = out + qb * S0 + rrem + (long long)col * S2 + offs;
                float4 v = make_float4(acc[iq * 4 + 0][j], acc[iq * 4 + 1][j],
                                       acc[iq * 4 + 2][j], acc[iq * 4 + 3][j]);
                *(float4*)op = v;
            }
        }
    }
}

// ---------------------------------------------------------------------------
extern "C" void kernel_launch(void* const* d_in, const int* in_sizes, int n_in,
                              void* d_out, int out_size) {
    const float* x   = (const float*)d_in[0];
    const float* lg  = (const float*)d_in[1];
    const float* lb  = (const float*)d_in[2];
    const float* W0a = (const float*)d_in[3];
    const float* b0a = (const float*)d_in[4];
    const float* W0b = (const float*)d_in[5];
    const float* b0b = (const float*)d_in[6];
    const float* c1w = (const float*)d_in[7];
    const float* c1b = (const float*)d_in[8];
    const float* W1a = (const float*)d_in[9];
    const float* b1a = (const float*)d_in[10];
    const float* W1b = (const float*)d_in[11];
    const float* b1b = (const float*)d_in[12];
    const float* c2w = (const float*)d_in[13];
    const float* c2b = (const float*)d_in[14];
    const float* W2a = (const float*)d_in[15];
    const float* b2a = (const float*)d_in[16];
    const float* W2b = (const float*)d_in[17];
    const float* b2b = (const float*)d_in[18];
    float* out = (float*)d_out;

    float *pWt0a, *pWt0b, *pWt1a, *pWt1b, *pWt2a, *pWt2b, *pWc1, *pWc2;
    float *pt0, *pg1, *pu1, *pg2, *pu2;
    cudaGetSymbolAddress((void**)&pWt0a, g_Wt0a);
    cudaGetSymbolAddress((void**)&pWt0b, g_Wt0b);
    cudaGetSymbolAddress((void**)&pWt1a, g_Wt1a);
    cudaGetSymbolAddress((void**)&pWt1b, g_Wt1b);
    cudaGetSymbolAddress((void**)&pWt2a, g_Wt2a);
    cudaGetSymbolAddress((void**)&pWt2b, g_Wt2b);
    cudaGetSymbolAddress((void**)&pWc1, g_Wc1);
    cudaGetSymbolAddress((void**)&pWc2, g_Wc2);
    cudaGetSymbolAddress((void**)&pt0, g_t0);
    cudaGetSymbolAddress((void**)&pg1, g_g1);
    cudaGetSymbolAddress((void**)&pu1, g_u1);
    cudaGetSymbolAddress((void**)&pg2, g_g2);
    cudaGetSymbolAddress((void**)&pu2, g_u2);

    stats_k<<<NB, 256>>>(x);
    prep_k<<<128, 256>>>(W0a, W0b, W1a, W1b, W2a, W2b, c1w, c2w);

    // scale 0: LN(x) @ tril(W0a)^T + b0a, hardswish  -> t0 (row-major B*T x 128)
    gemm_k<128, 128, 32, 8, 8, 128, true><<<2048, 256>>>(
        x, pWt0a, b0a, pt0, 1, 0, 1, 0, 1, 0, lg, lb);
    // t0 @ tril(W0b)^T + b0b -> out[b, j, t]  (transposed store), rows 0..127
    gemm_k<128, 128, 32, 8, 8, 128, false><<<2048, 256>>>(
        pt0, pWt0b, b0b, out, 0, 1, 128, 28672, 128, 0, nullptr, nullptr);

    // conv1: rows (b,s) contiguous K=256 -> g1[b, co, s]
    gemm_k<128, 128, 32, 8, 8, 256, false><<<1024, 256>>>(
        x, pWc1, c1b, pg1, 0, 1, 64, 8192, 64, 0, nullptr, nullptr);
    // triu(W1a)+hsw over time (rows b*128+co, K=64) -> u1 row-major
    gemm_k<128, 64, 32, 8, 4, 64, false><<<2048, 256>>>(
        pg1, pWt1a, b1a, pu1, 1, 0, 1, 0, 1, 0, nullptr, nullptr);
    // triu(W1b) -> out[b, 128+s, co], rows 128..191
    gemm_k<128, 64, 32, 8, 4, 64, false><<<2048, 256>>>(
        pu1, pWt1b, b1b, out, 0, 1, 128, 28672, 128, 16384, nullptr, nullptr);

    // conv2: rows (b,s) contiguous K=512 -> g2[b, co, s]
    gemm_k<128, 128, 32, 8, 8, 512, false><<<512, 256>>>(
        x, pWc2, c2b, pg2, 0, 1, 32, 4096, 32, 0, nullptr, nullptr);
    // triu(W2a)+hsw (K=32) -> u2
    gemm_k<128, 32, 32, 4, 4, 32, false><<<2048, 256>>>(
        pg2, pWt2a, b2a, pu2, 1, 0, 1, 0, 1, 0, nullptr, nullptr);
    // triu(W2b) -> out[b, 192+s, co], rows 192..223
    gemm_k<128, 32, 32, 4, 4, 32, false><<<2048, 256>>>(
        pu2, pWt2b, b2b, out, 0, 1, 128, 28672, 128, 24576, nullptr, nullptr);
}

// round 6
// speedup vs baseline: 1.9207x; 1.9207x over previous
#include <cuda_runtime.h>
#include <cuda_fp16.h>
#include <cstdint>

// ---------------------------------------------------------------------------
// MultiScaleTimeMixer via warp-level HMMA (mma.sync m16n8k16 fp16, fp32 acc).
// 3-pass fp16 hi/lo split for ~fp32 accuracy. B=2048, T=128, C=128.
// ---------------------------------------------------------------------------

#define NB 2048

// ---- fp32 intermediates ----
__device__ float g_mu[NB];
__device__ float g_rs[NB];
__device__ float g_t0[(long long)NB * 128 * 128];
__device__ float g_g1[(long long)NB * 128 * 64];
__device__ float g_u1[(long long)NB * 128 * 64];
__device__ float g_g2[(long long)NB * 128 * 32];
__device__ float g_u2[(long long)NB * 128 * 32];

// ---- fp16 hi/lo weights, [N][K] row-major (K-major for B^T) ----
__device__ __align__(16) __half g_B0ah[16384], g_B0al[16384];
__device__ __align__(16) __half g_B0bh[16384], g_B0bl[16384];
__device__ __align__(16) __half g_B1ah[4096],  g_B1al[4096];
__device__ __align__(16) __half g_B1bh[4096],  g_B1bl[4096];
__device__ __align__(16) __half g_B2ah[1024],  g_B2al[1024];
__device__ __align__(16) __half g_B2bh[1024],  g_B2bl[1024];
__device__ __align__(16) __half g_Bc1h[128*256], g_Bc1l[128*256];
__device__ __align__(16) __half g_Bc2h[128*512], g_Bc2l[128*512];

__device__ __forceinline__ uint32_t smem_u32(const void* p) {
    uint32_t a;
    asm("{ .reg .u64 t; cvta.to.shared.u64 t, %1; cvt.u32.u64 %0, t; }"
        : "=r"(a) : "l"(p));
    return a;
}

#define LDSM4(r, addr)                                                          \
    asm volatile("ldmatrix.sync.aligned.m8n8.x4.shared.b16 {%0,%1,%2,%3}, [%4];" \
        : "=r"((r)[0]), "=r"((r)[1]), "=r"((r)[2]), "=r"((r)[3]) : "r"(addr))

#define MMA16816(d, a, b0, b1)                                                  \
    asm volatile("mma.sync.aligned.m16n8k16.row.col.f32.f16.f16.f32 "           \
        "{%0,%1,%2,%3}, {%4,%5,%6,%7}, {%8,%9}, {%0,%1,%2,%3};"                 \
        : "+f"((d)[0]), "+f"((d)[1]), "+f"((d)[2]), "+f"((d)[3])                 \
        : "r"((a)[0]), "r"((a)[1]), "r"((a)[2]), "r"((a)[3]), "r"(b0), "r"(b1))

__device__ __forceinline__ uint32_t pack2h(__half a, __half b) {
    return (uint32_t)__half_as_ushort(a) | ((uint32_t)__half_as_ushort(b) << 16);
}
__device__ __forceinline__ void hsplit(float v, __half& h, __half& l) {
    h = __float2half_rn(v);
    l = __float2half_rn(v - __half2float(h));
}
__device__ __forceinline__ float hswish(float v) {
    return v * fminf(fmaxf(v + 3.f, 0.f), 6.f) * (1.f / 6.f);
}

// ---------------------------------------------------------------------------
// Per-batch LayerNorm stats
// ---------------------------------------------------------------------------
__global__ void stats_k(const float* __restrict__ x) {
    int b = blockIdx.x;
    const float4* xp = (const float4*)(x + (long long)b * 16384);
    float s = 0.f, q = 0.f;
    for (int i = threadIdx.x; i < 4096; i += 256) {
        float4 v = xp[i];
        s += v.x + v.y + v.z + v.w;
        q += v.x * v.x + v.y * v.y + v.z * v.z + v.w * v.w;
    }
    #pragma unroll
    for (int o = 16; o > 0; o >>= 1) {
        s += __shfl_down_sync(0xffffffffu, s, o);
        q += __shfl_down_sync(0xffffffffu, q, o);
    }
    __shared__ float ss[8], qs[8];
    int w = threadIdx.x >> 5, l = threadIdx.x & 31;
    if (l == 0) { ss[w] = s; qs[w] = q; }
    __syncthreads();
    if (threadIdx.x == 0) {
        float S = 0.f, Q = 0.f;
        #pragma unroll
        for (int i = 0; i < 8; i++) { S += ss[i]; Q += qs[i]; }
        float mu = S * (1.f / 16384.f);
        float var = Q * (1.f / 16384.f) - mu * mu;
        g_mu[b] = mu;
        g_rs[b] = rsqrtf(var + 1e-5f);
    }
}

// ---------------------------------------------------------------------------
// Weight prep: tril mask + fp16 hi/lo split; conv weights -> [co][tt*128+c]
// ---------------------------------------------------------------------------
__global__ void prep_k(const float* __restrict__ W0a, const float* __restrict__ W0b,
                       const float* __restrict__ W1a, const float* __restrict__ W1b,
                       const float* __restrict__ W2a, const float* __restrict__ W2b,
                       const float* __restrict__ c1w, const float* __restrict__ c2w) {
    int tid = blockIdx.x * blockDim.x + threadIdx.x;
    int stride = gridDim.x * blockDim.x;
    for (int i = tid; i < 16384; i += stride) {
        int n = i >> 7, k = i & 127;
        float m = (k <= n) ? 1.f : 0.f;
        hsplit(m * W0a[i], g_B0ah[i], g_B0al[i]);
        hsplit(m * W0b[i], g_B0bh[i], g_B0bl[i]);
    }
    for (int i = tid; i < 4096; i += stride) {
        int n = i >> 6, k = i & 63;
        float m = (k <= n) ? 1.f : 0.f;
        hsplit(m * W1a[i], g_B1ah[i], g_B1al[i]);
        hsplit(m * W1b[i], g_B1bh[i], g_B1bl[i]);
    }
    for (int i = tid; i < 1024; i += stride) {
        int n = i >> 5, k = i & 31;
        float m = (k <= n) ? 1.f : 0.f;
        hsplit(m * W2a[i], g_B2ah[i], g_B2al[i]);
        hsplit(m * W2b[i], g_B2bh[i], g_B2bl[i]);
    }
    for (int i = tid; i < 128 * 256; i += stride) {
        int co = i >> 8, k = i & 255;
        int tt = k >> 7, c = k & 127;
        hsplit(c1w[co * 256 + c * 2 + tt], g_Bc1h[i], g_Bc1l[i]);
    }
    for (int i = tid; i < 128 * 512; i += stride) {
        int co = i >> 9, k = i & 511;
        int tt = k >> 7, c = k & 127;
        hsplit(c2w[co * 512 + c * 4 + tt], g_Bc2h[i], g_Bc2l[i]);
    }
}

// ---------------------------------------------------------------------------
// HMMA GEMM: D[128-row tile, N] = A[M,KTOT] @ B^T, B stored [N][KTOT] fp16
// hi/lo. 3-pass: Ah*Bh + Ah*Bl + Al*Bh. fp32 accum.
//   NORM: LayerNorm folded into A load (stage 0a).
//   mode 0: out[row*N + col]
//   mode 1: out[(row>>rbsh)*S0 + (row & mask) + col*S2 + offs], via smem
//           transpose tile for coalesced stores.
// ---------------------------------------------------------------------------
template<int N, int KTOT, bool NORM>
__global__ __launch_bounds__(256)
void hgemm_k(const float* __restrict__ A,
             const __half* __restrict__ Bh,
             const __half* __restrict__ Bl,
             const float* __restrict__ bias,
             float* __restrict__ out,
             int hsw, int mode, int rbsh, int S0, int S2, int offs,
             const float* __restrict__ gamma, const float* __restrict__ beta) {
    constexpr int NCHUNK = (KTOT + 63) / 64;
    constexpr int NG16 = N / 16;
    constexpr int SA = 72;                 // half-stride per row (144B)
    constexpr int ABYTES = 128 * SA * 2;   // 18432
    constexpr int BBYTES = N * SA * 2;

    extern __shared__ char dsm[];
    __shared__ float s_bias[N];

    const int tid = threadIdx.x;
    const int wid = tid >> 5, lane = tid & 31;
    const int r0 = wid * 16;
    const long long row0 = (long long)blockIdx.x * 128;

    char* pAh = dsm;
    char* pAl = dsm + ABYTES;
    char* pBh = dsm + 2 * ABYTES;
    char* pBl = pBh + BBYTES;
    const uint32_t uAh = smem_u32(pAh);
    const uint32_t uAl = uAh + ABYTES;
    const uint32_t uBh = uAh + 2 * ABYTES;
    const uint32_t uBl = uBh + BBYTES;

    if (tid < N) s_bias[tid] = bias[tid];

    // per-thread ldmatrix base offsets (bytes)
    const uint32_t aOff =
        (uint32_t)((r0 + ((lane >> 3) & 1) * 8 + (lane & 7)) * SA + (lane >> 4) * 8) * 2;
    const uint32_t bOff =
        (uint32_t)(((lane >> 4) * 8 + (lane & 7)) * SA + ((lane >> 3) & 1) * 8) * 2;

    float acc[NG16 * 2][4];
    #pragma unroll
    for (int i = 0; i < NG16 * 2; i++)
        #pragma unroll
        for (int j = 0; j < 4; j++) acc[i][j] = 0.f;

    for (int c = 0; c < NCHUNK; c++) {
        const int k0 = c * 64;
        // ---- stage A: 128 x 64 fp32 -> fp16 hi/lo ----
        #pragma unroll
        for (int qq = 0; qq < 8; qq++) {
            int q = qq * 256 + tid;
            int r = q >> 4, kq = q & 15;
            int col = k0 + kq * 4;
            float4 v = make_float4(0.f, 0.f, 0.f, 0.f);
            if (KTOT >= 64 || col < KTOT)
                v = *(const float4*)(A + (row0 + r) * KTOT + col);
            if (NORM) {
                long long grow = row0 + r;
                int b = (int)(grow >> 7);
                float mu = g_mu[b], rs = g_rs[b];
                int t = (int)(grow & 127);
                float4 g  = *(const float4*)(gamma + t * 128 + col);
                float4 be = *(const float4*)(beta + t * 128 + col);
                v.x = (v.x - mu) * rs * g.x + be.x;
                v.y = (v.y - mu) * rs * g.y + be.y;
                v.z = (v.z - mu) * rs * g.z + be.z;
                v.w = (v.w - mu) * rs * g.w + be.w;
            }
            __half hx, hy, hz, hw, lx, ly, lz, lw;
            hsplit(v.x, hx, lx); hsplit(v.y, hy, ly);
            hsplit(v.z, hz, lz); hsplit(v.w, hw, lw);
            uint32_t off = (uint32_t)(r * SA + kq * 4) * 2;
            uint2 uh; uh.x = pack2h(hx, hy); uh.y = pack2h(hz, hw);
            uint2 ul; ul.x = pack2h(lx, ly); ul.y = pack2h(lz, lw);
            *(uint2*)(pAh + off) = uh;
            *(uint2*)(pAl + off) = ul;
        }
        // ---- stage B hi/lo: N x 64 fp16 copy ----
        #pragma unroll
        for (int qq = 0; qq < N / 32; qq++) {
            int q = qq * 256 + tid;
            int n = q >> 3, kq = q & 7;
            int col = k0 + kq * 8;
            uint4 vh = make_uint4(0, 0, 0, 0), vl = make_uint4(0, 0, 0, 0);
            if (KTOT >= 64 || col < KTOT) {
                vh = *(const uint4*)(Bh + n * KTOT + col);
                vl = *(const uint4*)(Bl + n * KTOT + col);
            }
            uint32_t off = (uint32_t)(n * SA + kq * 8) * 2;
            *(uint4*)(pBh + off) = vh;
            *(uint4*)(pBl + off) = vl;
        }
        __syncthreads();
        // ---- compute: 4 k16 steps ----
        #pragma unroll
        for (int kk = 0; kk < 4; kk++) {
            uint32_t ah[4], al[4];
            LDSM4(ah, uAh + aOff + kk * 32);
            LDSM4(al, uAl + aOff + kk * 32);
            #pragma unroll
            for (int g = 0; g < NG16; g++) {
                uint32_t bh[4], bl[4];
                LDSM4(bh, uBh + bOff + g * (16 * SA * 2) + kk * 32);
                MMA16816(acc[g * 2 + 0], ah, bh[0], bh[1]);
                MMA16816(acc[g * 2 + 1], ah, bh[2], bh[3]);
                MMA16816(acc[g * 2 + 0], al, bh[0], bh[1]);
                MMA16816(acc[g * 2 + 1], al, bh[2], bh[3]);
                LDSM4(bl, uBl + bOff + g * (16 * SA * 2) + kk * 32);
                MMA16816(acc[g * 2 + 0], ah, bl[0], bl[1]);
                MMA16816(acc[g * 2 + 1], ah, bl[2], bl[3]);
            }
        }
        __syncthreads();
    }

    // ---- epilogue ----
    const int cbase = 2 * (lane & 3);
    const int ra = r0 + (lane >> 2);
    if (mode == 0) {
        #pragma unroll
        for (int g = 0; g < NG16; g++) {
            #pragma unroll
            for (int j = 0; j < 2; j++) {
                int cc = g * 16 + j * 8 + cbase;
                float b0 = s_bias[cc], b1 = s_bias[cc + 1];
                float* ac = acc[g * 2 + j];
                float v0 = ac[0] + b0, v1 = ac[1] + b1;
                float v2 = ac[2] + b0, v3 = ac[3] + b1;
                if (hsw) { v0 = hswish(v0); v1 = hswish(v1); v2 = hswish(v2); v3 = hswish(v3); }
                *(float2*)(out + (row0 + ra) * N + cc) = make_float2(v0, v1);
                *(float2*)(out + (row0 + ra + 8) * N + cc) = make_float2(v2, v3);
            }
        }
    } else {
        // transpose through smem for coalesced scatter
        float* tile = (float*)dsm;
        const int ts = N + 1;
        #pragma unroll
        for (int g = 0; g < NG16; g++) {
            #pragma unroll
            for (int j = 0; j < 2; j++) {
                int cc = g * 16 + j * 8 + cbase;
                float b0 = s_bias[cc], b1 = s_bias[cc + 1];
                float* ac = acc[g * 2 + j];
                float v0 = ac[0] + b0, v1 = ac[1] + b1;
                float v2 = ac[2] + b0, v3 = ac[3] + b1;
                if (hsw) { v0 = hswish(v0); v1 = hswish(v1); v2 = hswish(v2); v3 = hswish(v3); }
                tile[ra * ts + cc] = v0;
                tile[ra * ts + cc + 1] = v1;
                tile[(ra + 8) * ts + cc] = v2;
                tile[(ra + 8) * ts + cc + 1] = v3;
            }
        }
        __syncthreads();
        const int mask = (1 << rbsh) - 1;
        #pragma unroll
        for (int it = 0; it < N / 2; it++) {
            int q = it * 256 + tid;
            int rr = q & 127, cc = q >> 7;
            float v = tile[rr * ts + cc];
            long long grow = row0 + rr;
            long long qb = grow >> rbsh;
            int rrem = (int)(grow & mask);
            out[qb * (long long)S0 + rrem + (long long)cc * S2 + offs] = v;
        }
    }
}

// ---------------------------------------------------------------------------
extern "C" void kernel_launch(void* const* d_in, const int* in_sizes, int n_in,
                              void* d_out, int out_size) {
    const float* x   = (const float*)d_in[0];
    const float* lg  = (const float*)d_in[1];
    const float* lb  = (const float*)d_in[2];
    const float* W0a = (const float*)d_in[3];
    const float* b0a = (const float*)d_in[4];
    const float* W0b = (const float*)d_in[5];
    const float* b0b = (const float*)d_in[6];
    const float* c1w = (const float*)d_in[7];
    const float* c1b = (const float*)d_in[8];
    const float* W1a = (const float*)d_in[9];
    const float* b1a = (const float*)d_in[10];
    const float* W1b = (const float*)d_in[11];
    const float* b1b = (const float*)d_in[12];
    const float* c2w = (const float*)d_in[13];
    const float* c2b = (const float*)d_in[14];
    const float* W2a = (const float*)d_in[15];
    const float* b2a = (const float*)d_in[16];
    const float* W2b = (const float*)d_in[17];
    const float* b2b = (const float*)d_in[18];
    float* out = (float*)d_out;

    float *pt0, *pg1, *pu1, *pg2, *pu2;
    __half *p0ah, *p0al, *p0bh, *p0bl, *p1ah, *p1al, *p1bh, *p1bl;
    __half *p2ah, *p2al, *p2bh, *p2bl, *pc1h, *pc1l, *pc2h, *pc2l;
    cudaGetSymbolAddress((void**)&pt0, g_t0);
    cudaGetSymbolAddress((void**)&pg1, g_g1);
    cudaGetSymbolAddress((void**)&pu1, g_u1);
    cudaGetSymbolAddress((void**)&pg2, g_g2);
    cudaGetSymbolAddress((void**)&pu2, g_u2);
    cudaGetSymbolAddress((void**)&p0ah, g_B0ah); cudaGetSymbolAddress((void**)&p0al, g_B0al);
    cudaGetSymbolAddress((void**)&p0bh, g_B0bh); cudaGetSymbolAddress((void**)&p0bl, g_B0bl);
    cudaGetSymbolAddress((void**)&p1ah, g_B1ah); cudaGetSymbolAddress((void**)&p1al, g_B1al);
    cudaGetSymbolAddress((void**)&p1bh, g_B1bh); cudaGetSymbolAddress((void**)&p1bl, g_B1bl);
    cudaGetSymbolAddress((void**)&p2ah, g_B2ah); cudaGetSymbolAddress((void**)&p2al, g_B2al);
    cudaGetSymbolAddress((void**)&p2bh, g_B2bh); cudaGetSymbolAddress((void**)&p2bl, g_B2bl);
    cudaGetSymbolAddress((void**)&pc1h, g_Bc1h); cudaGetSymbolAddress((void**)&pc1l, g_Bc1l);
    cudaGetSymbolAddress((void**)&pc2h, g_Bc2h); cudaGetSymbolAddress((void**)&pc2l, g_Bc2l);

    // dynamic smem: mainloop = 2*18432 + 2*N*144; epilogue tile = 128*(N+1)*4
    const int ds128 = 2 * 18432 + 2 * 128 * 144;  // 73728 (tile 66048 fits)
    const int ds64  = 2 * 18432 + 2 * 64 * 144;   // 55296 (tile 33280 fits)
    const int ds32  = 2 * 18432 + 2 * 32 * 144;   // 46080 (tile 16896 fits)
    cudaFuncSetAttribute(hgemm_k<128, 128, true>,
                         cudaFuncAttributeMaxDynamicSharedMemorySize, ds128);
    cudaFuncSetAttribute(hgemm_k<128, 128, false>,
                         cudaFuncAttributeMaxDynamicSharedMemorySize, ds128);
    cudaFuncSetAttribute(hgemm_k<128, 256, false>,
                         cudaFuncAttributeMaxDynamicSharedMemorySize, ds128);
    cudaFuncSetAttribute(hgemm_k<128, 512, false>,
                         cudaFuncAttributeMaxDynamicSharedMemorySize, ds128);
    cudaFuncSetAttribute(hgemm_k<64, 64, false>,
                         cudaFuncAttributeMaxDynamicSharedMemorySize, ds64);
    cudaFuncSetAttribute(hgemm_k<32, 32, false>,
                         cudaFuncAttributeMaxDynamicSharedMemorySize, ds32);

    stats_k<<<NB, 256>>>(x);
    prep_k<<<128, 256>>>(W0a, W0b, W1a, W1b, W2a, W2b, c1w, c2w);

    // scale 0: hsw(LN(x) @ W0a^T + b0a) -> t0 (row-major)
    hgemm_k<128, 128, true><<<2048, 256, ds128>>>(
        x, p0ah, p0al, b0a, pt0, 1, 0, 0, 0, 0, 0, lg, lb);
    // t0 @ W0b^T + b0b -> out[b, j, t], rows 0..127
    hgemm_k<128, 128, false><<<2048, 256, ds128>>>(
        pt0, p0bh, p0bl, b0b, out, 0, 1, 7, 28672, 128, 0, nullptr, nullptr);

    // conv1 (reshape GEMM, K=256) -> g1[b, co, s]
    hgemm_k<128, 256, false><<<1024, 256, ds128>>>(
        x, pc1h, pc1l, c1b, pg1, 0, 1, 6, 8192, 64, 0, nullptr, nullptr);
    // triu1a + hsw -> u1 row-major
    hgemm_k<64, 64, false><<<2048, 256, ds64>>>(
        pg1, p1ah, p1al, b1a, pu1, 1, 0, 0, 0, 0, 0, nullptr, nullptr);
    // triu1b -> out[b, 128+s, co], rows 128..191
    hgemm_k<64, 64, false><<<2048, 256, ds64>>>(
        pu1, p1bh, p1bl, b1b, out, 0, 1, 7, 28672, 128, 16384, nullptr, nullptr);

    // conv2 (K=512) -> g2[b, co, s]
    hgemm_k<128, 512, false><<<512, 256, ds128>>>(
        x, pc2h, pc2l, c2b, pg2, 0, 1, 5, 4096, 32, 0, nullptr, nullptr);
    // triu2a + hsw -> u2
    hgemm_k<32, 32, false><<<2048, 256, ds32>>>(
        pg2, p2ah, p2al, b2a, pu2, 1, 0, 0, 0, 0, 0, nullptr, nullptr);
    // triu2b -> out[b, 192+s, co], rows 192..223
    hgemm_k<32, 32, false><<<2048, 256, ds32>>>(
        pu2, p2bh, p2bl, b2b, out, 0, 1, 7, 28672, 128, 24576, nullptr, nullptr);
}